// round 7
// baseline (speedup 1.0000x reference)
#include <cuda_runtime.h>
#include <stdint.h>
#include <math.h>

// Problem shapes (fixed for this dataset entry)
#define B_    16
#define CH    512
#define HW    16384
#define C_    16              // selected classes
#define G_    32              // groups (CH/C_)
#define NP    120             // off-diagonal pairs
#define HNP   60              // pairs per thread-half
#define S_    2               // HW chunks per (b,g)
#define CHUNK (HW/S_)         // 8192
#define NBG   (B_*G_)         // 512
#define THREADS 256

#define SK        512                   // floats per channel per stage
#define NSTAGES   (CHUNK/SK)            // 16
#define NBUF      4                     // 4 x 32KB buffers = 128 KB smem
#define SMEM_FLOATS (NBUF*C_*SK)        // 32768 floats = 128 KB

// Scratch (static __device__ — no allocations allowed)
__device__ int   d_src[CH];              // [k*C_+cls] -> source channel in x
__device__ float d_wgh[CH];              // [k*C_+cls] -> sigmoid(|w|)
__device__ float d_part[NBG*S_*NP];      // partial Gram sums

__device__ __forceinline__ void cp_async16(unsigned int saddr, const void* gptr) {
    asm volatile("cp.async.cg.shared.global [%0], [%1], 16;" :: "r"(saddr), "l"(gptr));
}
__device__ __forceinline__ void cp_commit() {
    asm volatile("cp.async.commit_group;");
}
template<int N>
__device__ __forceinline__ void cp_wait() {
    asm volatile("cp.async.wait_group %0;" :: "n"(N));
}
__device__ __forceinline__ unsigned int smem_u32(const void* p) {
    unsigned int a;
    asm("{ .reg .u64 t; cvta.to.shared.u64 t, %1; cvt.u32.u64 %0, t; }" : "=r"(a) : "l"(p));
    return a;
}
// packed dual-lane fp32 FMA: d.lo += a.lo*b.lo; d.hi += a.hi*b.hi
#define FMA2(d, a, b) \
    asm("fma.rn.f32x2 %0, %1, %2, %0;" : "+l"(d) : "l"(a), "l"(b))

// ---------------------------------------------------------------------------
// Kernel 1: rank-based top-G selection, 8-way parallel per class.
// Grid = C_*8 CTAs; CTA = (class, channel-octant of 64). 512 threads: 8
// threads per channel, each comparing a 64-wide slice. |w| compared as
// integer bits (monotone for non-negative floats); stable tie-break d < c.
// ---------------------------------------------------------------------------
__global__ void z_prep_kernel(const float* __restrict__ cw, const int* __restrict__ sel) {
    __shared__ unsigned int sbits[CH];
    __shared__ int part[64][8];
    int t = threadIdx.x;
    int cls_idx = blockIdx.x >> 3;        // 0..15
    int co      = blockIdx.x & 7;         // channel octant
    int cls = sel[cls_idx];

    sbits[t] = __float_as_uint(fabsf(cw[cls*CH + t]));
    __syncthreads();

    int c = co*64 + (t >> 3);             // channel this thread helps rank
    int p = t & 7;                        // d-slice
    unsigned int mine = sbits[c];
    int cnt = 0;
#pragma unroll 8
    for (int dd = p*64; dd < p*64 + 64; dd++) {
        unsigned int o = sbits[dd];
        cnt += (o > mine) || (o == mine && dd < c);
    }
    part[t >> 3][p] = cnt;
    __syncthreads();

    if (t < 64) {
        int ch = co*64 + t;
        int rank = part[t][0]+part[t][1]+part[t][2]+part[t][3]
                 + part[t][4]+part[t][5]+part[t][6]+part[t][7];
        if (rank < G_) {
            float val = __uint_as_float(sbits[ch]);
            d_src[rank*C_ + cls_idx] = ch;
            d_wgh[rank*C_ + cls_idx] = 1.0f / (1.0f + expf(-val));
        }
    }
}

// ---------------------------------------------------------------------------
// Gram accumulate for one float4 (= 2 f32x2 lanes) per channel, pairs
// [QLO, QLO+60). Fully unrolled; constexpr-guarded.
// ---------------------------------------------------------------------------
template<int QLO>
__device__ __forceinline__ void accum60(unsigned long long* __restrict__ acc,
                                        const ulonglong2* __restrict__ v) {
    int q = 0;
#pragma unroll
    for (int i = 0; i < C_; i++) {
#pragma unroll
        for (int j = i+1; j < C_; j++) {
            if (q >= QLO && q < QLO + HNP) {
                FMA2(acc[q - QLO], v[i].x, v[j].x);
                FMA2(acc[q - QLO], v[i].y, v[j].y);
            }
            q++;
        }
    }
}

// ---------------------------------------------------------------------------
// Kernel 2: partial Gram per (b, g, chunk). cp.async pipeline with 4 x 32 KB
// buffers, 3 stages committed ahead -> 96 KB per SM in flight during compute
// (Little's law: loaded-DRAM latency ~2.5-4K cyc needs deep in-flight bytes).
// Pairs split across thread halves (warps 0-3: 0..59, warps 4-7: 60..119).
// ---------------------------------------------------------------------------
extern __shared__ float sA[];   // [NBUF][C_][SK]

__global__ void __launch_bounds__(THREADS, 1)
a0_gram_kernel(const float* __restrict__ x) {
    int bid = blockIdx.x;                 // 0 .. NBG*S_-1
    int bg  = bid >> 1;                   // S_ == 2
    int s   = bid & (S_-1);
    int b   = bg / G_;
    int g   = bg % G_;
    int t   = threadIdx.x;

    __shared__ int soff[C_];
    if (t < C_)
        soff[t] = d_src[g*C_ + t] * (HW/4);  // channel offset in float4 units
    __syncthreads();

    const float4* base = (const float4*)x + ((size_t)b * CH) * (HW/4) + (size_t)s * (CHUNK/4);
    int off[C_];
#pragma unroll
    for (int i = 0; i < C_; i++) off[i] = soff[i];

    unsigned int sbase = smem_u32(sA);

    // copy stage st into buffer buf: 2048 float4s; thread t copies 8 of them
    auto copy_stage = [&](int st, int buf) {
#pragma unroll
        for (int r = 0; r < 8; r++) {
            int idx = r*THREADS + t;          // 0..2047
            int ch  = idx >> 7;               // /128
            int pos = idx & 127;
            unsigned int daddr = sbase + (unsigned int)(((buf*C_ + ch)*SK + pos*4) * 4);
            cp_async16(daddr, (const void*)(base + off[ch] + st*(SK/4) + pos));
        }
        cp_commit();
    };

    int half = t >> 7;                    // 0: pairs 0..59, 1: pairs 60..119
    int kt   = t & 127;

    unsigned long long acc[HNP];
#pragma unroll
    for (int q = 0; q < HNP; q++) acc[q] = 0ull;

    auto compute_stage = [&](int st) {
        const ulonglong2* sp = (const ulonglong2*)(sA + ((st & (NBUF-1)) * C_) * SK);
        ulonglong2 v[C_];
#pragma unroll
        for (int i = 0; i < C_; i++) v[i] = sp[i*(SK/4) + kt];
        if (half == 0) accum60<0>(acc, v);
        else           accum60<HNP>(acc, v);
    };

    copy_stage(0, 0);
    copy_stage(1, 1);
    copy_stage(2, 2);

    for (int st = 0; st < NSTAGES - 2; st++) {
        cp_wait<2>();                     // stage st complete
        __syncthreads();                  // visible to all; prev compute done
        if (st + 3 < NSTAGES) copy_stage(st + 3, (st + 3) & (NBUF-1));
        compute_stage(st);
    }
    cp_wait<1>(); __syncthreads(); compute_stage(NSTAGES - 2);
    cp_wait<0>(); __syncthreads(); compute_stage(NSTAGES - 1);

    // collapse f32x2 lanes -> scalar
    float a[HNP];
#pragma unroll
    for (int q = 0; q < HNP; q++) {
        unsigned int lo, hi;
        asm("mov.b64 {%0, %1}, %2;" : "=r"(lo), "=r"(hi) : "l"(acc[q]));
        a[q] = __uint_as_float(lo) + __uint_as_float(hi);
    }
    // warp reduce
#pragma unroll
    for (int q = 0; q < HNP; q++) {
        float v = a[q];
#pragma unroll
        for (int o = 16; o > 0; o >>= 1)
            v += __shfl_down_sync(0xffffffffu, v, o);
        a[q] = v;
    }

    __syncthreads();
    float* red = sA;                      // reuse: [8][HNP]
    int warp = t >> 5, lane = t & 31;
    if (lane == 0) {
#pragma unroll
        for (int q = 0; q < HNP; q++) red[warp*HNP + q] = a[q];
    }
    __syncthreads();
    if (t < HNP) {                        // combine half0 (warps 0..3)
        float sum = red[0*HNP+t] + red[1*HNP+t] + red[2*HNP+t] + red[3*HNP+t];
        d_part[(size_t)bid*NP + t] = sum;
    } else if (t >= 64 && t < 64 + HNP) { // combine half1 (warps 4..7)
        int p = t - 64;
        float sum = red[4*HNP+p] + red[5*HNP+p] + red[6*HNP+p] + red[7*HNP+p];
        d_part[(size_t)bid*NP + HNP + p] = sum;
    }
}

// ---------------------------------------------------------------------------
// Kernel 3: fused combine + |.|*w_i*w_j + full reduction + normalization.
// ---------------------------------------------------------------------------
__global__ void reduce_kernel(float* __restrict__ out) {
    int bg = threadIdx.x;                 // 0..NBG-1
    int g  = bg % G_;
    const float* pa = d_part + (size_t)(2*bg)   * NP;
    const float* pb = d_part + (size_t)(2*bg+1) * NP;

    float w[C_];
#pragma unroll
    for (int i = 0; i < C_; i++) w[i] = d_wgh[g*C_ + i];

    float sum = 0.0f;
    int p = 0;
#pragma unroll
    for (int i = 0; i < C_; i++) {
#pragma unroll
        for (int j = i+1; j < C_; j++) {
            sum += fabsf(pa[p] + pb[p]) * (w[i] * w[j]);
            p++;
        }
    }

    __shared__ float sm[NBG];
    sm[bg] = sum;
    __syncthreads();
#pragma unroll
    for (int o = NBG/2; o > 0; o >>= 1) {
        if (threadIdx.x < o) sm[threadIdx.x] += sm[threadIdx.x + o];
        __syncthreads();
    }
    if (threadIdx.x == 0)
        out[0] = sm[0] * (1.0f / ((float)(HW-1) * (float)NP * (float)B_));
}

extern "C" void kernel_launch(void* const* d_in, const int* in_sizes, int n_in,
                              void* d_out, int out_size) {
    const float* x   = (const float*)d_in[0];
    const float* cw  = (const float*)d_in[1];
    const int*   sel = (const int*)d_in[2];
    float* out = (float*)d_out;

    cudaFuncSetAttribute(a0_gram_kernel,
                         cudaFuncAttributeMaxDynamicSharedMemorySize,
                         SMEM_FLOATS * sizeof(float));

    z_prep_kernel<<<C_*8, CH>>>(cw, sel);
    a0_gram_kernel<<<NBG*S_, THREADS, SMEM_FLOATS * sizeof(float)>>>(x);
    reduce_kernel<<<1, NBG>>>(out);
}